// round 11
// baseline (speedup 1.0000x reference)
#include <cuda_runtime.h>

// SelfAttention_61804579389661 — GB300 sm_103a — Round 11
//
// Algebraic simplification: softmax over a size-1 axis is identically 1.0,
// so attention == 1 and context[b,u] = sum_s hidden_states[b,s,u]. The
// entire tanh/GEMM pipeline in the reference is dead code.
//
// Converged design (R3-R10): strided U-chunk decomposition, 512 thr/block,
// zero cross-block communication, ones in epilogue. Unroll 8->16 raised
// HBM 6314->6371 GB/s at flat regs (R10). R11 tests the saturation point:
// #pragma unroll 32 + two independent accumulator chains (even/odd) so the
// longer body doesn't lengthen the FADD RAW chain while ptxas front-batches
// more LDG.128s.
//
// Output layout (out_size = 98304 fp32):
//   [0      .. 32767 ]  context   (B=32, U=1024)
//   [32768  .. 98303 ]  attention (B=32, S=2048, 1) == 1.0f

#define BB 32
#define SS 2048
#define UU 1024
#define U4 (UU / 4)        // 256 float4 per row
#define NCHUNK 16          // U-chunks per batch row
#define C4 (U4 / NCHUNK)   // 16 float4 lanes per chunk
#define NT 512             // threads per block
#define SPHASE (NT / C4)   // 32 s-strides per block

__global__ void __launch_bounds__(NT) fused_kernel(const float4* __restrict__ hs,
                                                   float* __restrict__ out) {
    const int b = blockIdx.x;   // 0..31
    const int y = blockIdx.y;   // 0..15
    const int t = threadIdx.x;  // 0..511

    // ---- block (b, y): sum hs[b, :, y*64 : y*64+64] over all S ----
    const int lane = t & (C4 - 1);      // 0..15 -> float4 column in chunk
    const int srow = t >> 4;            // 0..31 -> starting s, stride 32

    const float4* __restrict__ base =
        hs + ((size_t)b * SS + srow) * U4 + y * C4 + lane;

    float4 a0 = make_float4(0.f, 0.f, 0.f, 0.f);
    float4 a1 = make_float4(0.f, 0.f, 0.f, 0.f);
#pragma unroll 32
    for (int s = 0; s < SS / SPHASE; s += 2) {          // 64 iters, 2 per step
        float4 v0 = base[(size_t)s * SPHASE * U4];
        float4 v1 = base[(size_t)(s + 1) * SPHASE * U4];
        a0.x += v0.x; a0.y += v0.y; a0.z += v0.z; a0.w += v0.w;
        a1.x += v1.x; a1.y += v1.y; a1.z += v1.z; a1.w += v1.w;
    }
    float4 acc = make_float4(a0.x + a1.x, a0.y + a1.y, a0.z + a1.z, a0.w + a1.w);

    // ---- deterministic in-block reduction of the 32 s-phases ----
    __shared__ float4 smem[NT];
    smem[t] = acc;
    __syncthreads();

    if (t < C4) {
        float4 r = make_float4(0.f, 0.f, 0.f, 0.f);
#pragma unroll
        for (int k = 0; k < SPHASE; ++k) {              // fixed order
            float4 v = smem[k * C4 + t];
            r.x += v.x; r.y += v.y; r.z += v.z; r.w += v.w;
        }
        ((float4*)out)[b * U4 + y * C4 + t] = r;
    }

    // ---- epilogue: attention region = 1.0, spread over all 512 blocks ----
    // 16384 float4 total / 512 blocks = 32 float4 per block (threads 32..63,
    // disjoint from the context-writing threads 0..15).
    if (t >= 32 && t < 64) {
        float4* ones = (float4*)(out + BB * UU);
        ones[(b * NCHUNK + y) * 32 + (t - 32)] = make_float4(1.f, 1.f, 1.f, 1.f);
    }
}

extern "C" void kernel_launch(void* const* d_in, const int* in_sizes, int n_in,
                              void* d_out, int out_size) {
    // Inputs: [0]=s_prev, [1]=hidden_states, [2]=Ww, [3]=Wb, [4]=Uw, [5]=Ub,
    //         [6]=Vw, [7]=Vb. Only hidden_states is live.
    const float4* hs = (const float4*)d_in[1];
    float* out = (float*)d_out;

    dim3 grid(BB, NCHUNK);
    fused_kernel<<<grid, NT>>>(hs, out);
}

// round 12
// speedup vs baseline: 1.1420x; 1.1420x over previous
#include <cuda_runtime.h>

// SelfAttention_61804579389661 — GB300 sm_103a — FINAL (= R10, session best:
// 42.75us kernel, 6371 GB/s = 98.5% of the measured streaming-read floor)
//
// Algebraic simplification: softmax over a size-1 axis is identically 1.0,
// so attention == 1 and context[b,u] = sum_s hidden_states[b,s,u]. The
// entire tanh/GEMM pipeline in the reference is dead code; the problem is a
// pure 256 MiB read-reduce, bandwidth-bound.
//
// Converged design, with the measured evidence per axis (R3-R11):
//  - strided U-chunk decomposition: 6.26-6.37 TB/s vs 5.98-6.0 TB/s for
//    contiguous-per-block, at both high and low occupancy;
//  - zero cross-block communication (last-block-reduce tails cost ~2 us;
//    separate finalize launch cost ~5 us);
//  - 512 threads/block -> 8192 warps, ~85% occ, single wave;
//  - simple dependent-index loads with #pragma unroll 16 (ptxas-scheduled):
//    unroll 8 = 6314, unroll 16 = 6371 GB/s; manual register batching (R5)
//    and two-chain unroll-32 (R11: regs 36, occ 71%, 5525 GB/s) both regress;
//  - __ldcs neutral (stream is 2x L2 capacity either way);
//  - all-ones attention written in the epilogue of the same launch.
//
// Output layout (out_size = 98304 fp32):
//   [0      .. 32767 ]  context   (B=32, U=1024)
//   [32768  .. 98303 ]  attention (B=32, S=2048, 1) == 1.0f

#define BB 32
#define SS 2048
#define UU 1024
#define U4 (UU / 4)        // 256 float4 per row
#define NCHUNK 16          // U-chunks per batch row
#define C4 (U4 / NCHUNK)   // 16 float4 lanes per chunk
#define NT 512             // threads per block
#define SPHASE (NT / C4)   // 32 s-strides per block

__global__ void __launch_bounds__(NT) fused_kernel(const float4* __restrict__ hs,
                                                   float* __restrict__ out) {
    const int b = blockIdx.x;   // 0..31
    const int y = blockIdx.y;   // 0..15
    const int t = threadIdx.x;  // 0..511

    // ---- block (b, y): sum hs[b, :, y*64 : y*64+64] over all S ----
    const int lane = t & (C4 - 1);      // 0..15 -> float4 column in chunk
    const int srow = t >> 4;            // 0..31 -> starting s, stride 32

    const float4* __restrict__ base =
        hs + ((size_t)b * SS + srow) * U4 + y * C4 + lane;

    float4 acc = make_float4(0.f, 0.f, 0.f, 0.f);
#pragma unroll 16
    for (int s = 0; s < SS / SPHASE; ++s) {             // 64 iters, stride 32 rows
        float4 v = base[(size_t)s * SPHASE * U4];
        acc.x += v.x; acc.y += v.y; acc.z += v.z; acc.w += v.w;
    }

    // ---- deterministic in-block reduction of the 32 s-phases ----
    __shared__ float4 smem[NT];
    smem[t] = acc;
    __syncthreads();

    if (t < C4) {
        float4 r = make_float4(0.f, 0.f, 0.f, 0.f);
#pragma unroll
        for (int k = 0; k < SPHASE; ++k) {              // fixed order
            float4 v = smem[k * C4 + t];
            r.x += v.x; r.y += v.y; r.z += v.z; r.w += v.w;
        }
        ((float4*)out)[b * U4 + y * C4 + t] = r;
    }

    // ---- epilogue: attention region = 1.0, spread over all 512 blocks ----
    // 16384 float4 total / 512 blocks = 32 float4 per block (threads 32..63,
    // disjoint from the context-writing threads 0..15).
    if (t >= 32 && t < 64) {
        float4* ones = (float4*)(out + BB * UU);
        ones[(b * NCHUNK + y) * 32 + (t - 32)] = make_float4(1.f, 1.f, 1.f, 1.f);
    }
}

extern "C" void kernel_launch(void* const* d_in, const int* in_sizes, int n_in,
                              void* d_out, int out_size) {
    // Inputs: [0]=s_prev, [1]=hidden_states, [2]=Ww, [3]=Wb, [4]=Uw, [5]=Ub,
    //         [6]=Vw, [7]=Vb. Only hidden_states is live.
    const float4* hs = (const float4*)d_in[1];
    float* out = (float*)d_out;

    dim3 grid(BB, NCHUNK);
    fused_kernel<<<grid, NT>>>(hs, out);
}